// round 3
// baseline (speedup 1.0000x reference)
#include <cuda_runtime.h>

// RWKV v4 single-token forward, persistent kernel, round 3.
// vs R2: (1) grid barrier = per-block slot store + scan-poll (no single-address
// atomic serialization); (2) per-layer elementwise params + state rows staged
// into shared memory via cp.async, double-buffered, prefetched one layer ahead
// so they are never on the dependent chain.

#define E    1024
#define HH   4096
#define NL   24
#define NV   50277
#define T    1024
#define WPB  32
#define NPAR 16

// ---- persistent device scratch ----
__device__ float g_kvrp[2][3 * E];
__device__ float g_op[2][E];
__device__ float g_fkp[2][HH];
__device__ float g_frp[2][E];
__device__ float g_fvp[4][E];
__device__ volatile int g_slot[256];   // per-block arrival counters; memset per launch

struct P {
    const float *ctx, *state, *ln0w, *ln0b, *ln1w, *ln1b, *ln2w, *ln2b;
    const float *td, *tf, *tmk, *tmv, *tmr, *kw, *vw, *rw, *ow;
    const float *ftmk, *ftmr, *fkw, *frw, *fvw, *lnoutw, *lnoutb, *head;
    float* out;
    int nb;
    int ws;
};

// contention-free grid barrier: distinct-slot release stores + warp-0 scan poll
__device__ __forceinline__ void grid_sync(int nb, int s) {
    __threadfence();
    __syncthreads();
    if (threadIdx.x == 0) g_slot[blockIdx.x] = s;
    if (threadIdx.x < 32) {
        for (;;) {
            int ok = 1;
            for (int j = threadIdx.x; j < nb; j += 32) ok &= (g_slot[j] >= s);
            if (__all_sync(0xFFFFFFFFu, ok)) break;
            __nanosleep(32);
        }
    }
    __threadfence();
    __syncthreads();
}

__device__ __forceinline__ void block_reduce2(float& a, float& b, float* sr) {
    #pragma unroll
    for (int o = 16; o; o >>= 1) {
        a += __shfl_down_sync(0xFFFFFFFFu, a, o);
        b += __shfl_down_sync(0xFFFFFFFFu, b, o);
    }
    int w = threadIdx.x >> 5, l = threadIdx.x & 31;
    __syncthreads();
    if (l == 0) { sr[w] = a; sr[w + WPB] = b; }
    __syncthreads();
    if (threadIdx.x == 0) {
        float sa = 0.f, sb2 = 0.f;
        #pragma unroll
        for (int i = 0; i < WPB; i++) { sa += sr[i]; sb2 += sr[i + WPB]; }
        sr[2 * WPB] = sa; sr[2 * WPB + 1] = sb2;
    }
    __syncthreads();
    a = sr[2 * WPB];
    b = sr[2 * WPB + 1];
}

template <int N4>
__device__ __forceinline__ float warp_dot(const float* __restrict__ w,
                                          const float* x, int lane) {
    const float4* __restrict__ w4 = (const float4*)w;
    const float4* x4 = (const float4*)x;
    float acc0 = 0.f, acc1 = 0.f;
    #pragma unroll
    for (int u = 0; u < N4; u += 2) {
        float4 a = __ldg(&w4[lane + 32 * u]);
        float4 bx = x4[lane + 32 * u];
        acc0 += a.x * bx.x + a.y * bx.y + a.z * bx.z + a.w * bx.w;
        if (u + 1 < N4) {
            float4 a2 = __ldg(&w4[lane + 32 * (u + 1)]);
            float4 bx2 = x4[lane + 32 * (u + 1)];
            acc1 += a2.x * bx2.x + a2.y * bx2.y + a2.z * bx2.z + a2.w * bx2.w;
        }
    }
    float acc = acc0 + acc1;
    #pragma unroll
    for (int o = 16; o; o >>= 1) acc += __shfl_down_sync(0xFFFFFFFFu, acc, o);
    return acc;
}

__device__ __forceinline__ void cpa16(float* smem_dst, const float* g) {
    unsigned saddr = (unsigned)__cvta_generic_to_shared(smem_dst);
    asm volatile("cp.async.cg.shared.global [%0], [%1], 16;" :: "r"(saddr), "l"(g));
}

__device__ __forceinline__ const float* par_src(const P& p, int l, int a) {
    const float* st = p.state + (size_t)l * 5 * E;
    switch (a) {
        case 0:  return p.ln1w + l * E;
        case 1:  return p.ln1b + l * E;
        case 2:  return p.tmk + l * E;
        case 3:  return p.tmv + l * E;
        case 4:  return p.tmr + l * E;
        case 5:  return st + E;          // sprev
        case 6:  return p.tf + l * E;
        case 7:  return p.td + l * E;
        case 8:  return st + 2 * E;      // aa
        case 9:  return st + 3 * E;      // bb
        case 10: return st + 4 * E;      // pp
        case 11: return p.ln2w + l * E;
        case 12: return p.ln2b + l * E;
        case 13: return p.ftmk + l * E;
        case 14: return p.ftmr + l * E;
        default: return st;              // s0
    }
}

// prefetch all per-layer param/state vectors for layer l1 (or lnout for l1==NL)
__device__ __forceinline__ void prefetch_layer(const P& p, int l1, float* dst) {
    if (l1 < NL) {
        for (int t = threadIdx.x; t < NPAR * 256; t += T) {
            int a = t >> 8, i = (t & 255) << 2;
            cpa16(dst + a * E + i, par_src(p, l1, a) + i);
        }
    } else if (l1 == NL) {
        for (int t = threadIdx.x; t < 512; t += T) {
            int a = t >> 8, i = (t & 255) << 2;
            cpa16(dst + a * E + i, (a ? p.lnoutb : p.lnoutw) + i);
        }
    }
    asm volatile("cp.async.commit_group;" ::: "memory");
}

#define CP_WAIT() asm volatile("cp.async.wait_group 0;" ::: "memory")

#define SMEM_FLOATS (E + HH + 128 + 2 * NPAR * E)

__global__ void __launch_bounds__(T, 1) rwkv_kernel(P p) {
    extern __shared__ float smem[];
    float* sx   = smem;                 // residual stream [E]
    float* sop  = smem + E;             // operand buffer [HH]
    float* sred = smem + E + HH;        // [128]
    float* par0 = smem + E + HH + 128;  // [2][NPAR][E]

    const int tid = threadIdx.x, lane = tid & 31, warp = tid >> 5;
    const int gw = blockIdx.x * WPB + warp;
    const int NW = p.nb * WPB;
    const bool w0 = (p.ws && blockIdx.x == 0);
    float* outS = p.out + NV;
    int ss = 0, buf = 0;

    // prefetch layer 0 params while doing LN0
    prefetch_layer(p, 0, par0);

    float s = 0.f, s2 = 0.f;
    for (int i = tid; i < E; i += T) { float v = p.ctx[i]; sop[i] = v; s += v; s2 += v * v; }
    block_reduce2(s, s2, sred);
    {
        float mu = s * (1.f / E);
        float rs = rsqrtf(s2 * (1.f / E) - mu * mu + 1e-5f);
        for (int i = tid; i < E; i += T)
            sx[i] = (sop[i] - mu) * rs * p.ln0w[i] + p.ln0b[i];
    }
    CP_WAIT();
    __syncthreads();

    for (int l = 0; l < NL; l++) {
        const float* pr = par0 + buf * NPAR * E;

        // ======== Stage A: combine prev FFN + LN1 + time-mix + k/v/r GEMV ========
        if (l > 0) {
            for (int i = tid; i < E; i += T) {
                float fr = 1.f / (1.f + __expf(-(g_frp[0][i] + g_frp[1][i])));
                sx[i] += fr * (g_fvp[0][i] + g_fvp[1][i] + g_fvp[2][i] + g_fvp[3][i]);
            }
        }
        s = 0.f; s2 = 0.f;
        for (int i = tid; i < E; i += T) { float v = sx[i]; s += v; s2 += v * v; }
        block_reduce2(s, s2, sred);
        {
            float mu = s * (1.f / E);
            float rs = rsqrtf(s2 * (1.f / E) - mu * mu + 1e-5f);
            for (int i = tid; i < E; i += T) {
                float xn = (sx[i] - mu) * rs * pr[0 * E + i] + pr[1 * E + i];
                float spv = pr[5 * E + i];
                float a = pr[2 * E + i], b = pr[3 * E + i], c = pr[4 * E + i];
                sop[i]         = xn * a + spv * (1.f - a);
                sop[E + i]     = xn * b + spv * (1.f - b);
                sop[2 * E + i] = xn * c + spv * (1.f - c);
                if (w0) outS[(size_t)(5 * l + 1) * E + i] = xn;
            }
        }
        __syncthreads();
        // prefetch next layer's params; overlaps with GEMV streaming below
        prefetch_layer(p, l + 1, par0 + (buf ^ 1) * NPAR * E);
        {
            const float* Wk = p.kw + (size_t)l * E * E;
            const float* Wv = p.vw + (size_t)l * E * E;
            const float* Wr = p.rw + (size_t)l * E * E;
            for (int t = gw; t < 6144; t += NW) {
                int h = t & 1, r = t >> 1, m = r >> 10, i = r & 1023;
                const float* w = (m == 0 ? Wk : (m == 1 ? Wv : Wr)) + (size_t)i * E + h * 512;
                float acc = warp_dot<4>(w, sop + m * E + h * 512, lane);
                if (lane == 0) g_kvrp[h][m * E + i] = acc;
            }
        }
        grid_sync(p.nb, ++ss);

        // ======== Stage B: WKV + ow GEMV ========
        {
            for (int i = tid; i < E; i += T) {
                float k  = g_kvrp[0][i] + g_kvrp[1][i];
                float v  = g_kvrp[0][E + i] + g_kvrp[1][E + i];
                float rr = g_kvrp[0][2 * E + i] + g_kvrp[1][2 * E + i];
                float A = pr[8 * E + i], B = pr[9 * E + i], Pp = pr[10 * E + i];
                float ww = pr[6 * E + i] + k;
                float q = fmaxf(Pp, ww);
                float e1 = __expf(Pp - q), e2 = __expf(ww - q);
                float num = e1 * A + e2 * v, den = e1 * B + e2;
                float r = 1.f / (1.f + __expf(-rr));
                sop[i] = r * num / den;
                if (w0) {
                    float ww2 = Pp + pr[7 * E + i];
                    float p2 = fmaxf(ww2, k);
                    float e1b = __expf(ww2 - p2), e2b = __expf(k - p2);
                    outS[(size_t)(5 * l + 2) * E + i] = e1b * A + e2b * v;
                    outS[(size_t)(5 * l + 3) * E + i] = e1b * B + e2b;
                    outS[(size_t)(5 * l + 4) * E + i] = p2;
                }
            }
        }
        __syncthreads();
        {
            const float* OW = p.ow + (size_t)l * E * E;
            for (int t = gw; t < 2048; t += NW) {
                int h = t & 1, i = t >> 1;
                float acc = warp_dot<4>(OW + (size_t)i * E + h * 512, sop + h * 512, lane);
                if (lane == 0) g_op[h][i] = acc;
            }
        }
        grid_sync(p.nb, ++ss);

        // ======== Stage C: x += ow; LN2 + chan-mix + fk/fr GEMV ========
        for (int i = tid; i < E; i += T) sx[i] += g_op[0][i] + g_op[1][i];
        s = 0.f; s2 = 0.f;
        for (int i = tid; i < E; i += T) { float v = sx[i]; s += v; s2 += v * v; }
        block_reduce2(s, s2, sred);
        {
            float mu = s * (1.f / E);
            float rs = rsqrtf(s2 * (1.f / E) - mu * mu + 1e-5f);
            for (int i = tid; i < E; i += T) {
                float xn2 = (sx[i] - mu) * rs * pr[11 * E + i] + pr[12 * E + i];
                float sv = pr[15 * E + i];
                float a = pr[13 * E + i], b = pr[14 * E + i];
                sop[i]     = xn2 * a + sv * (1.f - a);
                sop[E + i] = xn2 * b + sv * (1.f - b);
                if (w0) outS[(size_t)(5 * l + 0) * E + i] = xn2;
            }
        }
        __syncthreads();
        {
            const float* FK = p.fkw + (size_t)l * HH * E;
            const float* FR = p.frw + (size_t)l * E * E;
            for (int t = gw; t < 10240; t += NW) {
                if (t < 8192) {
                    int h = t & 1, i = t >> 1;
                    float acc = warp_dot<4>(FK + (size_t)i * E + h * 512, sop + h * 512, lane);
                    if (lane == 0) g_fkp[h][i] = acc;
                } else {
                    int t2 = t - 8192;
                    int h = t2 & 1, i = t2 >> 1;
                    float acc = warp_dot<4>(FR + (size_t)i * E + h * 512, sop + E + h * 512, lane);
                    if (lane == 0) g_frp[h][i] = acc;
                }
            }
        }
        grid_sync(p.nb, ++ss);

        // ======== Stage D: kk = relu^2(fk); fv GEMV ========
        for (int i = tid; i < HH; i += T) {
            float a = fmaxf(g_fkp[0][i] + g_fkp[1][i], 0.f);
            sop[i] = a * a;
        }
        __syncthreads();
        {
            const float* FV = p.fvw + (size_t)l * E * HH;
            for (int t = gw; t < 4096; t += NW) {
                int c = t & 3, i = t >> 2;
                float acc = warp_dot<8>(FV + (size_t)i * HH + c * E, sop + c * E, lane);
                if (lane == 0) g_fvp[c][i] = acc;
            }
        }
        grid_sync(p.nb, ++ss);

        CP_WAIT();   // next-layer params resident before next iteration uses them
        buf ^= 1;
    }

    // ======== final: combine last FFN, LN_out, head GEMV ========
    const float* pr = par0 + buf * NPAR * E;   // slots 0,1 = lnoutw, lnoutb
    for (int i = tid; i < E; i += T) {
        float fr = 1.f / (1.f + __expf(-(g_frp[0][i] + g_frp[1][i])));
        sx[i] += fr * (g_fvp[0][i] + g_fvp[1][i] + g_fvp[2][i] + g_fvp[3][i]);
    }
    s = 0.f; s2 = 0.f;
    for (int i = tid; i < E; i += T) { float v = sx[i]; s += v; s2 += v * v; }
    block_reduce2(s, s2, sred);
    {
        float mu = s * (1.f / E);
        float rs = rsqrtf(s2 * (1.f / E) - mu * mu + 1e-5f);
        for (int i = tid; i < E; i += T)
            sop[i] = (sx[i] - mu) * rs * pr[i] + pr[E + i];
    }
    __syncthreads();
    for (int t = gw; t < NV; t += NW) {
        float acc = warp_dot<8>(p.head + (size_t)t * E, sop, lane);
        if (lane == 0) p.out[t] = acc;
    }
}

extern "C" void kernel_launch(void* const* d_in, const int* in_sizes, int n_in,
                              void* d_out, int out_size) {
    (void)in_sizes; (void)n_in;
    P p;
    p.ctx    = (const float*)d_in[0];
    p.state  = (const float*)d_in[1];
    p.ln0w   = (const float*)d_in[2];
    p.ln0b   = (const float*)d_in[3];
    p.ln1w   = (const float*)d_in[4];
    p.ln1b   = (const float*)d_in[5];
    p.ln2w   = (const float*)d_in[6];
    p.ln2b   = (const float*)d_in[7];
    p.td     = (const float*)d_in[8];
    p.tf     = (const float*)d_in[9];
    p.tmk    = (const float*)d_in[10];
    p.tmv    = (const float*)d_in[11];
    p.tmr    = (const float*)d_in[12];
    p.kw     = (const float*)d_in[13];
    p.vw     = (const float*)d_in[14];
    p.rw     = (const float*)d_in[15];
    p.ow     = (const float*)d_in[16];
    p.ftmk   = (const float*)d_in[17];
    p.ftmr   = (const float*)d_in[18];
    p.fkw    = (const float*)d_in[19];
    p.frw    = (const float*)d_in[20];
    p.fvw    = (const float*)d_in[21];
    p.lnoutw = (const float*)d_in[22];
    p.lnoutb = (const float*)d_in[23];
    p.head   = (const float*)d_in[24];
    p.out    = (float*)d_out;

    int dev = 0;
    cudaGetDevice(&dev);
    int nsm = 0;
    cudaDeviceGetAttribute(&nsm, cudaDevAttrMultiProcessorCount, dev);
    if (nsm <= 0) nsm = 148;
    if (nsm > 256) nsm = 256;
    p.nb = nsm;
    p.ws = (out_size >= NV + 5 * NL * E) ? 1 : 0;

    static int smem_set = 0;
    if (!smem_set) {
        cudaFuncSetAttribute(rwkv_kernel, cudaFuncAttributeMaxDynamicSharedMemorySize,
                             SMEM_FLOATS * sizeof(float));
        smem_set = 1;
    }

    void* baddr = nullptr;
    cudaGetSymbolAddress(&baddr, (const void*)g_slot);
    cudaMemsetAsync(baddr, 0, sizeof(int) * 256, 0);

    rwkv_kernel<<<nsm, T, SMEM_FLOATS * sizeof(float)>>>(p);
}

// round 4
// speedup vs baseline: 1.2615x; 1.2615x over previous
#include <cuda_runtime.h>

// RWKV v4 single-token forward, persistent kernel, round 4.
// vs R3: (1) barrier reverted to R2's atomic arrival + single-word generation
// poll (scan-poll barrier was the R3 regression); (2) NEW: each warp issues
// prefetch.global.L2 for exactly the weight rows it will process in the NEXT
// stage, right before the grid barrier, overlapping barrier/elementwise dead
// time with DRAM->L2 weight movement.

#define E    1024
#define HH   4096
#define NL   24
#define NV   50277
#define T    1024
#define WPB  32
#define NPAR 16

// ---- persistent device scratch ----
__device__ float g_kvrp[2][3 * E];
__device__ float g_op[2][E];
__device__ float g_fkp[2][HH];
__device__ float g_frp[2][E];
__device__ float g_fvp[4][E];
__device__ unsigned int g_bar[2];   // {count, generation}; memset per launch

struct P {
    const float *ctx, *state, *ln0w, *ln0b, *ln1w, *ln1b, *ln2w, *ln2b;
    const float *td, *tf, *tmk, *tmv, *tmr, *kw, *vw, *rw, *ow;
    const float *ftmk, *ftmr, *fkw, *frw, *fvw, *lnoutw, *lnoutb, *head;
    float* out;
    int nb;
    int ws;
};

__device__ __forceinline__ void grid_sync(int nb) {
    __syncthreads();
    if (threadIdx.x == 0) {
        unsigned int gen = ((volatile unsigned int*)g_bar)[1];
        __threadfence();
        if (atomicAdd(&g_bar[0], 1u) == (unsigned int)(nb - 1)) {
            atomicExch(&g_bar[0], 0u);
            __threadfence();
            atomicAdd(&g_bar[1], 1u);
        } else {
            while (((volatile unsigned int*)g_bar)[1] == gen) { __nanosleep(64); }
        }
        __threadfence();
    }
    __syncthreads();
}

__device__ __forceinline__ void block_reduce2(float& a, float& b, float* sr) {
    #pragma unroll
    for (int o = 16; o; o >>= 1) {
        a += __shfl_down_sync(0xFFFFFFFFu, a, o);
        b += __shfl_down_sync(0xFFFFFFFFu, b, o);
    }
    int w = threadIdx.x >> 5, l = threadIdx.x & 31;
    __syncthreads();
    if (l == 0) { sr[w] = a; sr[w + WPB] = b; }
    __syncthreads();
    if (threadIdx.x == 0) {
        float sa = 0.f, sb2 = 0.f;
        #pragma unroll
        for (int i = 0; i < WPB; i++) { sa += sr[i]; sb2 += sr[i + WPB]; }
        sr[2 * WPB] = sa; sr[2 * WPB + 1] = sb2;
    }
    __syncthreads();
    a = sr[2 * WPB];
    b = sr[2 * WPB + 1];
}

template <int N4>
__device__ __forceinline__ float warp_dot(const float* __restrict__ w,
                                          const float* x, int lane) {
    const float4* __restrict__ w4 = (const float4*)w;
    const float4* x4 = (const float4*)x;
    float acc0 = 0.f, acc1 = 0.f;
    #pragma unroll
    for (int u = 0; u < N4; u += 2) {
        float4 a = __ldg(&w4[lane + 32 * u]);
        float4 bx = x4[lane + 32 * u];
        acc0 += a.x * bx.x + a.y * bx.y + a.z * bx.z + a.w * bx.w;
        if (u + 1 < N4) {
            float4 a2 = __ldg(&w4[lane + 32 * (u + 1)]);
            float4 bx2 = x4[lane + 32 * (u + 1)];
            acc1 += a2.x * bx2.x + a2.y * bx2.y + a2.z * bx2.z + a2.w * bx2.w;
        }
    }
    float acc = acc0 + acc1;
    #pragma unroll
    for (int o = 16; o; o >>= 1) acc += __shfl_down_sync(0xFFFFFFFFu, acc, o);
    return acc;
}

// prefetch `lines` 128B cache lines starting at w into L2 (one line per lane)
__device__ __forceinline__ void pf_l2(const float* w, int lines, int lane) {
    if (lane < lines)
        asm volatile("prefetch.global.L2 [%0];" :: "l"((const char*)w + lane * 128));
}

__device__ __forceinline__ void cpa16(float* smem_dst, const float* g) {
    unsigned saddr = (unsigned)__cvta_generic_to_shared(smem_dst);
    asm volatile("cp.async.cg.shared.global [%0], [%1], 16;" :: "r"(saddr), "l"(g));
}

__device__ __forceinline__ const float* par_src(const P& p, int l, int a) {
    const float* st = p.state + (size_t)l * 5 * E;
    switch (a) {
        case 0:  return p.ln1w + l * E;
        case 1:  return p.ln1b + l * E;
        case 2:  return p.tmk + l * E;
        case 3:  return p.tmv + l * E;
        case 4:  return p.tmr + l * E;
        case 5:  return st + E;
        case 6:  return p.tf + l * E;
        case 7:  return p.td + l * E;
        case 8:  return st + 2 * E;
        case 9:  return st + 3 * E;
        case 10: return st + 4 * E;
        case 11: return p.ln2w + l * E;
        case 12: return p.ln2b + l * E;
        case 13: return p.ftmk + l * E;
        case 14: return p.ftmr + l * E;
        default: return st;
    }
}

__device__ __forceinline__ void prefetch_layer(const P& p, int l1, float* dst) {
    if (l1 < NL) {
        for (int t = threadIdx.x; t < NPAR * 256; t += T) {
            int a = t >> 8, i = (t & 255) << 2;
            cpa16(dst + a * E + i, par_src(p, l1, a) + i);
        }
    } else if (l1 == NL) {
        for (int t = threadIdx.x; t < 512; t += T) {
            int a = t >> 8, i = (t & 255) << 2;
            cpa16(dst + a * E + i, (a ? p.lnoutb : p.lnoutw) + i);
        }
    }
    asm volatile("cp.async.commit_group;" ::: "memory");
}

#define CP_WAIT() asm volatile("cp.async.wait_group 0;" ::: "memory")

#define SMEM_FLOATS (E + HH + 128 + 2 * NPAR * E)

__global__ void __launch_bounds__(T, 1) rwkv_kernel(P p) {
    extern __shared__ float smem[];
    float* sx   = smem;
    float* sop  = smem + E;
    float* sred = smem + E + HH;
    float* par0 = smem + E + HH + 128;

    const int tid = threadIdx.x, lane = tid & 31, warp = tid >> 5;
    const int gw = blockIdx.x * WPB + warp;
    const int NW = p.nb * WPB;
    const bool w0 = (p.ws && blockIdx.x == 0);
    float* outS = p.out + NV;
    int buf = 0;

    prefetch_layer(p, 0, par0);

    // prefetch this warp's stage-A rows for layer 0 into L2 during LN0
    {
        const float* Wk = p.kw; const float* Wv = p.vw; const float* Wr = p.rw;
        for (int t = gw; t < 6144; t += NW) {
            int h = t & 1, r = t >> 1, m = r >> 10, i = r & 1023;
            const float* w = (m == 0 ? Wk : (m == 1 ? Wv : Wr)) + (size_t)i * E + h * 512;
            pf_l2(w, 16, lane);
        }
    }

    float s = 0.f, s2 = 0.f;
    for (int i = tid; i < E; i += T) { float v = p.ctx[i]; sop[i] = v; s += v; s2 += v * v; }
    block_reduce2(s, s2, sred);
    {
        float mu = s * (1.f / E);
        float rs = rsqrtf(s2 * (1.f / E) - mu * mu + 1e-5f);
        for (int i = tid; i < E; i += T)
            sx[i] = (sop[i] - mu) * rs * p.ln0w[i] + p.ln0b[i];
    }
    CP_WAIT();
    __syncthreads();

    for (int l = 0; l < NL; l++) {
        const float* pr = par0 + buf * NPAR * E;

        // ======== Stage A: combine prev FFN + LN1 + time-mix + k/v/r GEMV ========
        if (l > 0) {
            for (int i = tid; i < E; i += T) {
                float fr = 1.f / (1.f + __expf(-(g_frp[0][i] + g_frp[1][i])));
                sx[i] += fr * (g_fvp[0][i] + g_fvp[1][i] + g_fvp[2][i] + g_fvp[3][i]);
            }
        }
        s = 0.f; s2 = 0.f;
        for (int i = tid; i < E; i += T) { float v = sx[i]; s += v; s2 += v * v; }
        block_reduce2(s, s2, sred);
        {
            float mu = s * (1.f / E);
            float rs = rsqrtf(s2 * (1.f / E) - mu * mu + 1e-5f);
            for (int i = tid; i < E; i += T) {
                float xn = (sx[i] - mu) * rs * pr[0 * E + i] + pr[1 * E + i];
                float spv = pr[5 * E + i];
                float a = pr[2 * E + i], b = pr[3 * E + i], c = pr[4 * E + i];
                sop[i]         = xn * a + spv * (1.f - a);
                sop[E + i]     = xn * b + spv * (1.f - b);
                sop[2 * E + i] = xn * c + spv * (1.f - c);
                if (w0) outS[(size_t)(5 * l + 1) * E + i] = xn;
            }
        }
        __syncthreads();
        prefetch_layer(p, l + 1, par0 + (buf ^ 1) * NPAR * E);
        {
            const float* Wk = p.kw + (size_t)l * E * E;
            const float* Wv = p.vw + (size_t)l * E * E;
            const float* Wr = p.rw + (size_t)l * E * E;
            for (int t = gw; t < 6144; t += NW) {
                int h = t & 1, r = t >> 1, m = r >> 10, i = r & 1023;
                const float* w = (m == 0 ? Wk : (m == 1 ? Wv : Wr)) + (size_t)i * E + h * 512;
                float acc = warp_dot<4>(w, sop + m * E + h * 512, lane);
                if (lane == 0) g_kvrp[h][m * E + i] = acc;
            }
            // prefetch own stage-B rows (ow) into L2 before the barrier
            const float* OW = p.ow + (size_t)l * E * E;
            for (int t = gw; t < 2048; t += NW) {
                int h = t & 1, i = t >> 1;
                pf_l2(OW + (size_t)i * E + h * 512, 16, lane);
            }
        }
        grid_sync(p.nb);

        // ======== Stage B: WKV + ow GEMV ========
        {
            for (int i = tid; i < E; i += T) {
                float k  = g_kvrp[0][i] + g_kvrp[1][i];
                float v  = g_kvrp[0][E + i] + g_kvrp[1][E + i];
                float rr = g_kvrp[0][2 * E + i] + g_kvrp[1][2 * E + i];
                float A = pr[8 * E + i], B = pr[9 * E + i], Pp = pr[10 * E + i];
                float ww = pr[6 * E + i] + k;
                float q = fmaxf(Pp, ww);
                float e1 = __expf(Pp - q), e2 = __expf(ww - q);
                float num = e1 * A + e2 * v, den = e1 * B + e2;
                float r = 1.f / (1.f + __expf(-rr));
                sop[i] = r * num / den;
                if (w0) {
                    float ww2 = Pp + pr[7 * E + i];
                    float p2 = fmaxf(ww2, k);
                    float e1b = __expf(ww2 - p2), e2b = __expf(k - p2);
                    outS[(size_t)(5 * l + 2) * E + i] = e1b * A + e2b * v;
                    outS[(size_t)(5 * l + 3) * E + i] = e1b * B + e2b;
                    outS[(size_t)(5 * l + 4) * E + i] = p2;
                }
            }
        }
        __syncthreads();
        {
            const float* OW = p.ow + (size_t)l * E * E;
            for (int t = gw; t < 2048; t += NW) {
                int h = t & 1, i = t >> 1;
                float acc = warp_dot<4>(OW + (size_t)i * E + h * 512, sop + h * 512, lane);
                if (lane == 0) g_op[h][i] = acc;
            }
            // prefetch own stage-C rows (fkw, frw)
            const float* FK = p.fkw + (size_t)l * HH * E;
            const float* FR = p.frw + (size_t)l * E * E;
            for (int t = gw; t < 10240; t += NW) {
                if (t < 8192) {
                    int h = t & 1, i = t >> 1;
                    pf_l2(FK + (size_t)i * E + h * 512, 16, lane);
                } else {
                    int t2 = t - 8192;
                    int h = t2 & 1, i = t2 >> 1;
                    pf_l2(FR + (size_t)i * E + h * 512, 16, lane);
                }
            }
        }
        grid_sync(p.nb);

        // ======== Stage C: x += ow; LN2 + chan-mix + fk/fr GEMV ========
        for (int i = tid; i < E; i += T) sx[i] += g_op[0][i] + g_op[1][i];
        s = 0.f; s2 = 0.f;
        for (int i = tid; i < E; i += T) { float v = sx[i]; s += v; s2 += v * v; }
        block_reduce2(s, s2, sred);
        {
            float mu = s * (1.f / E);
            float rs = rsqrtf(s2 * (1.f / E) - mu * mu + 1e-5f);
            for (int i = tid; i < E; i += T) {
                float xn2 = (sx[i] - mu) * rs * pr[11 * E + i] + pr[12 * E + i];
                float sv = pr[15 * E + i];
                float a = pr[13 * E + i], b = pr[14 * E + i];
                sop[i]     = xn2 * a + sv * (1.f - a);
                sop[E + i] = xn2 * b + sv * (1.f - b);
                if (w0) outS[(size_t)(5 * l + 0) * E + i] = xn2;
            }
        }
        __syncthreads();
        {
            const float* FK = p.fkw + (size_t)l * HH * E;
            const float* FR = p.frw + (size_t)l * E * E;
            for (int t = gw; t < 10240; t += NW) {
                if (t < 8192) {
                    int h = t & 1, i = t >> 1;
                    float acc = warp_dot<4>(FK + (size_t)i * E + h * 512, sop + h * 512, lane);
                    if (lane == 0) g_fkp[h][i] = acc;
                } else {
                    int t2 = t - 8192;
                    int h = t2 & 1, i = t2 >> 1;
                    float acc = warp_dot<4>(FR + (size_t)i * E + h * 512, sop + E + h * 512, lane);
                    if (lane == 0) g_frp[h][i] = acc;
                }
            }
            // prefetch own stage-D rows (fvw quarter rows, 4KB = 32 lines)
            const float* FV = p.fvw + (size_t)l * E * HH;
            for (int t = gw; t < 4096; t += NW) {
                int c = t & 3, i = t >> 2;
                pf_l2(FV + (size_t)i * HH + c * E, 32, lane);
            }
        }
        grid_sync(p.nb);

        // ======== Stage D: kk = relu^2(fk); fv GEMV ========
        for (int i = tid; i < HH; i += T) {
            float a = fmaxf(g_fkp[0][i] + g_fkp[1][i], 0.f);
            sop[i] = a * a;
        }
        __syncthreads();
        {
            const float* FV = p.fvw + (size_t)l * E * HH;
            for (int t = gw; t < 4096; t += NW) {
                int c = t & 3, i = t >> 2;
                float acc = warp_dot<8>(FV + (size_t)i * HH + c * E, sop + c * E, lane);
                if (lane == 0) g_fvp[c][i] = acc;
            }
            // prefetch next layer's stage-A rows (kvr)
            if (l + 1 < NL) {
                const float* Wk = p.kw + (size_t)(l + 1) * E * E;
                const float* Wv = p.vw + (size_t)(l + 1) * E * E;
                const float* Wr = p.rw + (size_t)(l + 1) * E * E;
                for (int t = gw; t < 6144; t += NW) {
                    int h = t & 1, r = t >> 1, m = r >> 10, i = r & 1023;
                    const float* w = (m == 0 ? Wk : (m == 1 ? Wv : Wr)) + (size_t)i * E + h * 512;
                    pf_l2(w, 16, lane);
                }
            }
        }
        grid_sync(p.nb);

        CP_WAIT();
        buf ^= 1;
    }

    // ======== final: combine last FFN, LN_out, head GEMV ========
    const float* pr = par0 + buf * NPAR * E;
    for (int i = tid; i < E; i += T) {
        float fr = 1.f / (1.f + __expf(-(g_frp[0][i] + g_frp[1][i])));
        sx[i] += fr * (g_fvp[0][i] + g_fvp[1][i] + g_fvp[2][i] + g_fvp[3][i]);
    }
    s = 0.f; s2 = 0.f;
    for (int i = tid; i < E; i += T) { float v = sx[i]; s += v; s2 += v * v; }
    block_reduce2(s, s2, sred);
    {
        float mu = s * (1.f / E);
        float rs = rsqrtf(s2 * (1.f / E) - mu * mu + 1e-5f);
        for (int i = tid; i < E; i += T)
            sop[i] = (sx[i] - mu) * rs * pr[i] + pr[E + i];
    }
    __syncthreads();
    for (int t = gw; t < NV; t += NW) {
        float acc = warp_dot<8>(p.head + (size_t)t * E, sop, lane);
        if (lane == 0) p.out[t] = acc;
    }
}

extern "C" void kernel_launch(void* const* d_in, const int* in_sizes, int n_in,
                              void* d_out, int out_size) {
    (void)in_sizes; (void)n_in;
    P p;
    p.ctx    = (const float*)d_in[0];
    p.state  = (const float*)d_in[1];
    p.ln0w   = (const float*)d_in[2];
    p.ln0b   = (const float*)d_in[3];
    p.ln1w   = (const float*)d_in[4];
    p.ln1b   = (const float*)d_in[5];
    p.ln2w   = (const float*)d_in[6];
    p.ln2b   = (const float*)d_in[7];
    p.td     = (const float*)d_in[8];
    p.tf     = (const float*)d_in[9];
    p.tmk    = (const float*)d_in[10];
    p.tmv    = (const float*)d_in[11];
    p.tmr    = (const float*)d_in[12];
    p.kw     = (const float*)d_in[13];
    p.vw     = (const float*)d_in[14];
    p.rw     = (const float*)d_in[15];
    p.ow     = (const float*)d_in[16];
    p.ftmk   = (const float*)d_in[17];
    p.ftmr   = (const float*)d_in[18];
    p.fkw    = (const float*)d_in[19];
    p.frw    = (const float*)d_in[20];
    p.fvw    = (const float*)d_in[21];
    p.lnoutw = (const float*)d_in[22];
    p.lnoutb = (const float*)d_in[23];
    p.head   = (const float*)d_in[24];
    p.out    = (float*)d_out;

    int dev = 0;
    cudaGetDevice(&dev);
    int nsm = 0;
    cudaDeviceGetAttribute(&nsm, cudaDevAttrMultiProcessorCount, dev);
    if (nsm <= 0) nsm = 148;
    if (nsm > 256) nsm = 256;
    p.nb = nsm;
    p.ws = (out_size >= NV + 5 * NL * E) ? 1 : 0;

    cudaFuncSetAttribute(rwkv_kernel, cudaFuncAttributeMaxDynamicSharedMemorySize,
                         SMEM_FLOATS * sizeof(float));

    void* baddr = nullptr;
    cudaGetSymbolAddress(&baddr, g_bar);
    cudaMemsetAsync(baddr, 0, sizeof(unsigned int) * 2, 0);

    rwkv_kernel<<<nsm, T, SMEM_FLOATS * sizeof(float)>>>(p);
}

// round 5
// speedup vs baseline: 1.3827x; 1.0961x over previous
#include <cuda_runtime.h>

// RWKV v4 single-token forward, persistent kernel, round 5.
// vs R4/R2: whole-row GEMV tasks for k/v/r and ffn_k (single latency exposure,
// no partial combine), balanced explicit task assignment in stage C, __ldcs
// weight loads (read-once, evict-first), 4 accumulator chains, param staging
// kept, L2 weight prefetch dropped, R2 atomic barrier kept.

#define E    1024
#define HH   4096
#define NL   24
#define NV   50277
#define T    1024
#define WPB  32
#define NPAR 16

// ---- persistent device scratch ----
__device__ float g_kvr[3 * E];     // k, v, r (whole rows, no partials)
__device__ float g_op[2][E];       // ow half-row partials
__device__ float g_fk[HH];         // ffn_k pre-relu (whole rows)
__device__ float g_frp[2][E];      // ffn_r half-row partials
__device__ float g_fvp[4][E];      // ffn_v quarter-row partials
__device__ unsigned int g_bar[2];  // {count, generation}; memset per launch

struct P {
    const float *ctx, *state, *ln0w, *ln0b, *ln1w, *ln1b, *ln2w, *ln2b;
    const float *td, *tf, *tmk, *tmv, *tmr, *kw, *vw, *rw, *ow;
    const float *ftmk, *ftmr, *fkw, *frw, *fvw, *lnoutw, *lnoutb, *head;
    float* out;
    int nb;
    int ws;
};

__device__ __forceinline__ void grid_sync(int nb) {
    __syncthreads();
    if (threadIdx.x == 0) {
        unsigned int gen = ((volatile unsigned int*)g_bar)[1];
        __threadfence();
        if (atomicAdd(&g_bar[0], 1u) == (unsigned int)(nb - 1)) {
            atomicExch(&g_bar[0], 0u);
            __threadfence();
            atomicAdd(&g_bar[1], 1u);
        } else {
            while (((volatile unsigned int*)g_bar)[1] == gen) { __nanosleep(64); }
        }
        __threadfence();
    }
    __syncthreads();
}

__device__ __forceinline__ void block_reduce2(float& a, float& b, float* sr) {
    #pragma unroll
    for (int o = 16; o; o >>= 1) {
        a += __shfl_down_sync(0xFFFFFFFFu, a, o);
        b += __shfl_down_sync(0xFFFFFFFFu, b, o);
    }
    int w = threadIdx.x >> 5, l = threadIdx.x & 31;
    __syncthreads();
    if (l == 0) { sr[w] = a; sr[w + WPB] = b; }
    __syncthreads();
    if (threadIdx.x == 0) {
        float sa = 0.f, sb2 = 0.f;
        #pragma unroll
        for (int i = 0; i < WPB; i++) { sa += sr[i]; sb2 += sr[i + WPB]; }
        sr[2 * WPB] = sa; sr[2 * WPB + 1] = sb2;
    }
    __syncthreads();
    a = sr[2 * WPB];
    b = sr[2 * WPB + 1];
}

// warp dot over 128*N4 floats; weights streamed with .cs (read-once)
template <int N4>
__device__ __forceinline__ float warp_dot(const float* __restrict__ w,
                                          const float* x, int lane) {
    const float4* __restrict__ w4 = (const float4*)w;
    const float4* x4 = (const float4*)x;
    float a0 = 0.f, a1 = 0.f, a2 = 0.f, a3 = 0.f;
    #pragma unroll
    for (int u = 0; u < N4; u += 4) {
        float4 wa = __ldcs(&w4[lane + 32 * u]);
        float4 xa = x4[lane + 32 * u];
        a0 += wa.x * xa.x + wa.y * xa.y + wa.z * xa.z + wa.w * xa.w;
        if (u + 1 < N4) {
            float4 wb = __ldcs(&w4[lane + 32 * (u + 1)]);
            float4 xb = x4[lane + 32 * (u + 1)];
            a1 += wb.x * xb.x + wb.y * xb.y + wb.z * xb.z + wb.w * xb.w;
        }
        if (u + 2 < N4) {
            float4 wc = __ldcs(&w4[lane + 32 * (u + 2)]);
            float4 xc = x4[lane + 32 * (u + 2)];
            a2 += wc.x * xc.x + wc.y * xc.y + wc.z * xc.z + wc.w * xc.w;
        }
        if (u + 3 < N4) {
            float4 wd = __ldcs(&w4[lane + 32 * (u + 3)]);
            float4 xd = x4[lane + 32 * (u + 3)];
            a3 += wd.x * xd.x + wd.y * xd.y + wd.z * xd.z + wd.w * xd.w;
        }
    }
    float acc = (a0 + a1) + (a2 + a3);
    #pragma unroll
    for (int o = 16; o; o >>= 1) acc += __shfl_down_sync(0xFFFFFFFFu, acc, o);
    return acc;
}

__device__ __forceinline__ void cpa16(float* smem_dst, const float* g) {
    unsigned saddr = (unsigned)__cvta_generic_to_shared(smem_dst);
    asm volatile("cp.async.cg.shared.global [%0], [%1], 16;" :: "r"(saddr), "l"(g));
}

__device__ __forceinline__ const float* par_src(const P& p, int l, int a) {
    const float* st = p.state + (size_t)l * 5 * E;
    switch (a) {
        case 0:  return p.ln1w + l * E;
        case 1:  return p.ln1b + l * E;
        case 2:  return p.tmk + l * E;
        case 3:  return p.tmv + l * E;
        case 4:  return p.tmr + l * E;
        case 5:  return st + E;
        case 6:  return p.tf + l * E;
        case 7:  return p.td + l * E;
        case 8:  return st + 2 * E;
        case 9:  return st + 3 * E;
        case 10: return st + 4 * E;
        case 11: return p.ln2w + l * E;
        case 12: return p.ln2b + l * E;
        case 13: return p.ftmk + l * E;
        case 14: return p.ftmr + l * E;
        default: return st;
    }
}

__device__ __forceinline__ void prefetch_layer(const P& p, int l1, float* dst) {
    if (l1 < NL) {
        for (int t = threadIdx.x; t < NPAR * 256; t += T) {
            int a = t >> 8, i = (t & 255) << 2;
            cpa16(dst + a * E + i, par_src(p, l1, a) + i);
        }
    } else if (l1 == NL) {
        for (int t = threadIdx.x; t < 512; t += T) {
            int a = t >> 8, i = (t & 255) << 2;
            cpa16(dst + a * E + i, (a ? p.lnoutb : p.lnoutw) + i);
        }
    }
    asm volatile("cp.async.commit_group;" ::: "memory");
}

#define CP_WAIT() asm volatile("cp.async.wait_group 0;" ::: "memory")

#define SMEM_FLOATS (E + HH + 128 + 2 * NPAR * E)

__global__ void __launch_bounds__(T, 1) rwkv_kernel(P p) {
    extern __shared__ float smem[];
    float* sx   = smem;
    float* sop  = smem + E;
    float* sred = smem + E + HH;
    float* par0 = smem + E + HH + 128;

    const int tid = threadIdx.x, lane = tid & 31, warp = tid >> 5;
    const int gw = blockIdx.x * WPB + warp;
    const int NW = p.nb * WPB;
    const bool w0 = (p.ws && blockIdx.x == 0);
    float* outS = p.out + NV;
    int buf = 0;

    prefetch_layer(p, 0, par0);

    float s = 0.f, s2 = 0.f;
    for (int i = tid; i < E; i += T) { float v = p.ctx[i]; sop[i] = v; s += v; s2 += v * v; }
    block_reduce2(s, s2, sred);
    {
        float mu = s * (1.f / E);
        float rs = rsqrtf(s2 * (1.f / E) - mu * mu + 1e-5f);
        for (int i = tid; i < E; i += T)
            sx[i] = (sop[i] - mu) * rs * p.ln0w[i] + p.ln0b[i];
    }
    CP_WAIT();
    __syncthreads();

    for (int l = 0; l < NL; l++) {
        const float* pr = par0 + buf * NPAR * E;

        // ======== Stage A: combine prev FFN + LN1 + time-mix + k/v/r GEMV ========
        if (l > 0) {
            for (int i = tid; i < E; i += T) {
                float fr = 1.f / (1.f + __expf(-(g_frp[0][i] + g_frp[1][i])));
                sx[i] += fr * (g_fvp[0][i] + g_fvp[1][i] + g_fvp[2][i] + g_fvp[3][i]);
            }
        }
        s = 0.f; s2 = 0.f;
        for (int i = tid; i < E; i += T) { float v = sx[i]; s += v; s2 += v * v; }
        block_reduce2(s, s2, sred);
        {
            float mu = s * (1.f / E);
            float rs = rsqrtf(s2 * (1.f / E) - mu * mu + 1e-5f);
            for (int i = tid; i < E; i += T) {
                float xn = (sx[i] - mu) * rs * pr[0 * E + i] + pr[1 * E + i];
                float spv = pr[5 * E + i];
                float a = pr[2 * E + i], b = pr[3 * E + i], c = pr[4 * E + i];
                sop[i]         = xn * a + spv * (1.f - a);
                sop[E + i]     = xn * b + spv * (1.f - b);
                sop[2 * E + i] = xn * c + spv * (1.f - c);
                if (w0) outS[(size_t)(5 * l + 1) * E + i] = xn;
            }
        }
        __syncthreads();
        prefetch_layer(p, l + 1, par0 + (buf ^ 1) * NPAR * E);
        // whole-row k/v/r GEMVs: 3072 tasks, one per warp, single exposure
        if (gw < 3072) {
            int m = gw >> 10, i = gw & 1023;
            const float* W = (m == 0 ? p.kw : (m == 1 ? p.vw : p.rw)) + (size_t)l * E * E;
            float acc = warp_dot<8>(W + (size_t)i * E, sop + (m << 10), lane);
            if (lane == 0) g_kvr[gw] = acc;
        }
        grid_sync(p.nb);

        // ======== Stage B: WKV + ow GEMV (half rows) ========
        {
            for (int i = tid; i < E; i += T) {
                float k  = g_kvr[i];
                float v  = g_kvr[E + i];
                float rr = g_kvr[2 * E + i];
                float A = pr[8 * E + i], B = pr[9 * E + i], Pp = pr[10 * E + i];
                float ww = pr[6 * E + i] + k;
                float q = fmaxf(Pp, ww);
                float e1 = __expf(Pp - q), e2 = __expf(ww - q);
                float num = e1 * A + e2 * v, den = e1 * B + e2;
                float r = 1.f / (1.f + __expf(-rr));
                sop[i] = r * num / den;
                if (w0) {
                    float ww2 = Pp + pr[7 * E + i];
                    float p2 = fmaxf(ww2, k);
                    float e1b = __expf(ww2 - p2), e2b = __expf(k - p2);
                    outS[(size_t)(5 * l + 2) * E + i] = e1b * A + e2b * v;
                    outS[(size_t)(5 * l + 3) * E + i] = e1b * B + e2b;
                    outS[(size_t)(5 * l + 4) * E + i] = p2;
                }
            }
        }
        __syncthreads();
        if (gw < 2048) {
            int h = gw & 1, i = gw >> 1;
            const float* OW = p.ow + (size_t)l * E * E;
            float acc = warp_dot<4>(OW + (size_t)i * E + h * 512, sop + h * 512, lane);
            if (lane == 0) g_op[h][i] = acc;
        }
        grid_sync(p.nb);

        // ======== Stage C: x += ow; LN2 + chan-mix + fk (whole) / fr (half) ========
        for (int i = tid; i < E; i += T) sx[i] += g_op[0][i] + g_op[1][i];
        s = 0.f; s2 = 0.f;
        for (int i = tid; i < E; i += T) { float v = sx[i]; s += v; s2 += v * v; }
        block_reduce2(s, s2, sred);
        {
            float mu = s * (1.f / E);
            float rs = rsqrtf(s2 * (1.f / E) - mu * mu + 1e-5f);
            for (int i = tid; i < E; i += T) {
                float xn2 = (sx[i] - mu) * rs * pr[11 * E + i] + pr[12 * E + i];
                float sv = pr[15 * E + i];
                float a = pr[13 * E + i], b = pr[14 * E + i];
                sop[i]     = xn2 * a + sv * (1.f - a);
                sop[E + i] = xn2 * b + sv * (1.f - b);
                if (w0) outS[(size_t)(5 * l + 0) * E + i] = xn2;
            }
        }
        __syncthreads();
        {
            const float* FK = p.fkw + (size_t)l * HH * E;
            const float* FR = p.frw + (size_t)l * E * E;
            if (gw < 4096) {
                float acc = warp_dot<8>(FK + (size_t)gw * E, sop, lane);
                if (lane == 0) g_fk[gw] = acc;
            }
            // fr halves: 2048 tasks on warps [4096,4864) and [0,1280)
            int ft = (gw >= 4096) ? (gw - 4096) : (gw < 1280 ? 768 + gw : -1);
            if (ft >= 0 && ft < 2048) {
                int i = ft >> 1, h = ft & 1;
                float acc = warp_dot<4>(FR + (size_t)i * E + h * 512, sop + E + h * 512, lane);
                if (lane == 0) g_frp[h][i] = acc;
            }
        }
        grid_sync(p.nb);

        // ======== Stage D: kk = relu^2(fk); fv GEMV (quarter rows) ========
        for (int i = tid; i < HH; i += T) {
            float a = fmaxf(g_fk[i], 0.f);
            sop[i] = a * a;
        }
        __syncthreads();
        if (gw < 4096) {
            int c = gw & 3, i = gw >> 2;
            const float* FV = p.fvw + (size_t)l * E * HH;
            float acc = warp_dot<8>(FV + (size_t)i * HH + c * E, sop + c * E, lane);
            if (lane == 0) g_fvp[c][i] = acc;
        }
        grid_sync(p.nb);

        CP_WAIT();
        buf ^= 1;
    }

    // ======== final: combine last FFN, LN_out, head GEMV ========
    const float* pr = par0 + buf * NPAR * E;
    for (int i = tid; i < E; i += T) {
        float fr = 1.f / (1.f + __expf(-(g_frp[0][i] + g_frp[1][i])));
        sx[i] += fr * (g_fvp[0][i] + g_fvp[1][i] + g_fvp[2][i] + g_fvp[3][i]);
    }
    s = 0.f; s2 = 0.f;
    for (int i = tid; i < E; i += T) { float v = sx[i]; s += v; s2 += v * v; }
    block_reduce2(s, s2, sred);
    {
        float mu = s * (1.f / E);
        float rs = rsqrtf(s2 * (1.f / E) - mu * mu + 1e-5f);
        for (int i = tid; i < E; i += T)
            sop[i] = (sx[i] - mu) * rs * pr[i] + pr[E + i];
    }
    __syncthreads();
    for (int t = gw; t < NV; t += NW) {
        float acc = warp_dot<8>(p.head + (size_t)t * E, sop, lane);
        if (lane == 0) p.out[t] = acc;
    }
}

extern "C" void kernel_launch(void* const* d_in, const int* in_sizes, int n_in,
                              void* d_out, int out_size) {
    (void)in_sizes; (void)n_in;
    P p;
    p.ctx    = (const float*)d_in[0];
    p.state  = (const float*)d_in[1];
    p.ln0w   = (const float*)d_in[2];
    p.ln0b   = (const float*)d_in[3];
    p.ln1w   = (const float*)d_in[4];
    p.ln1b   = (const float*)d_in[5];
    p.ln2w   = (const float*)d_in[6];
    p.ln2b   = (const float*)d_in[7];
    p.td     = (const float*)d_in[8];
    p.tf     = (const float*)d_in[9];
    p.tmk    = (const float*)d_in[10];
    p.tmv    = (const float*)d_in[11];
    p.tmr    = (const float*)d_in[12];
    p.kw     = (const float*)d_in[13];
    p.vw     = (const float*)d_in[14];
    p.rw     = (const float*)d_in[15];
    p.ow     = (const float*)d_in[16];
    p.ftmk   = (const float*)d_in[17];
    p.ftmr   = (const float*)d_in[18];
    p.fkw    = (const float*)d_in[19];
    p.frw    = (const float*)d_in[20];
    p.fvw    = (const float*)d_in[21];
    p.lnoutw = (const float*)d_in[22];
    p.lnoutb = (const float*)d_in[23];
    p.head   = (const float*)d_in[24];
    p.out    = (float*)d_out;

    int dev = 0;
    cudaGetDevice(&dev);
    int nsm = 0;
    cudaDeviceGetAttribute(&nsm, cudaDevAttrMultiProcessorCount, dev);
    if (nsm <= 0) nsm = 148;
    if (nsm > 256) nsm = 256;
    p.nb = nsm;
    p.ws = (out_size >= NV + 5 * NL * E) ? 1 : 0;

    cudaFuncSetAttribute(rwkv_kernel, cudaFuncAttributeMaxDynamicSharedMemorySize,
                         SMEM_FLOATS * sizeof(float));

    void* baddr = nullptr;
    cudaGetSymbolAddress(&baddr, g_bar);
    cudaMemsetAsync(baddr, 0, sizeof(unsigned int) * 2, 0);

    rwkv_kernel<<<nsm, T, SMEM_FLOATS * sizeof(float)>>>(p);
}